// round 7
// baseline (speedup 1.0000x reference)
#include <cuda_runtime.h>

// Problem constants
#define BB 4
#define SS 2048
#define DD 512
#define HH 8
#define HD 64
#define MROWS (BB*SS)   // 8192

// Scratch (static device arrays -- allocation-free per harness rules)
__device__ float g_gate[BB*SS*DD];       // [b,s,d]   16 MB
__device__ float g_q[BB*HH*SS*HD];       // [b,h,s,d] 16 MB
__device__ float g_k[BB*HH*SS*HD];
__device__ float g_v[BB*HH*SS*HD];
__device__ float g_o[BB*SS*DD];          // [b,s,d] (attention out, already transposed back)
__device__ float g_ng[BB*SS*DD];         // layernorm(o) * gate

__device__ __forceinline__ float silu_f(float x) {
    return x / (1.0f + __expf(-x));
}

// ---------------------------------------------------------------------------
// Tiled SGEMM: C[M,N] = A[M,512] * W[N,512]^T (+bias, +epilogue)
// BM=BN=128, BK=16, 256 threads, 8x8 per thread.
// MODE 0: A = x, epilogue = silu(.)+scatter to gate/q/k/v
// MODE 1: A = g_ng, epilogue = +b2, write to out
// ---------------------------------------------------------------------------
template<int MODE>
__global__ void __launch_bounds__(256) gemm_kernel(
    const float* __restrict__ A_in,
    const float* __restrict__ W,
    const float* __restrict__ bias,
    float* __restrict__ out)
{
    __shared__ float As[16][132];
    __shared__ float Bs[16][132];

    const float* A = (MODE == 0) ? A_in : g_ng;

    const int tid  = threadIdx.x;
    const int tx   = tid & 15;       // N direction
    const int ty   = tid >> 4;       // M direction
    const int row0 = blockIdx.y * 128;
    const int col0 = blockIdx.x * 128;

    float acc[8][8];
    #pragma unroll
    for (int i = 0; i < 8; i++)
        #pragma unroll
        for (int j = 0; j < 8; j++) acc[i][j] = 0.0f;

    const int lr = tid >> 2;          // 0..63
    const int lk = (tid & 3) << 2;    // 0,4,8,12

    for (int k0 = 0; k0 < 512; k0 += 16) {
        #pragma unroll
        for (int l = 0; l < 2; l++) {
            int r = lr + l * 64;
            float4 av = *(const float4*)&A[(size_t)(row0 + r) * 512 + k0 + lk];
            As[lk + 0][r] = av.x; As[lk + 1][r] = av.y;
            As[lk + 2][r] = av.z; As[lk + 3][r] = av.w;
            float4 bv = *(const float4*)&W[(size_t)(col0 + r) * 512 + k0 + lk];
            Bs[lk + 0][r] = bv.x; Bs[lk + 1][r] = bv.y;
            Bs[lk + 2][r] = bv.z; Bs[lk + 3][r] = bv.w;
        }
        __syncthreads();

        #pragma unroll 8
        for (int kk = 0; kk < 16; kk++) {
            float ra[8], rb[8];
            *(float4*)&ra[0] = *(const float4*)&As[kk][ty * 8];
            *(float4*)&ra[4] = *(const float4*)&As[kk][ty * 8 + 4];
            *(float4*)&rb[0] = *(const float4*)&Bs[kk][tx * 8];
            *(float4*)&rb[4] = *(const float4*)&Bs[kk][tx * 8 + 4];
            #pragma unroll
            for (int i = 0; i < 8; i++)
                #pragma unroll
                for (int j = 0; j < 8; j++)
                    acc[i][j] += ra[i] * rb[j];
        }
        __syncthreads();
    }

    if (MODE == 0) {
        // silu + scatter: j = c*512 + head*64 + d  (c: 0=gate,1=q,2=k,3=v)
        #pragma unroll
        for (int ii = 0; ii < 8; ii++) {
            const int r = row0 + ty * 8 + ii;
            const int b = r >> 11;       // / 2048
            const int s = r & 2047;
            #pragma unroll
            for (int jj = 0; jj < 8; jj++) {
                const int j = col0 + tx * 8 + jj;
                float v = silu_f(acc[ii][jj] + bias[j]);
                const int c   = j >> 9;
                const int rem = j & 511;
                if (c == 0) {
                    g_gate[(size_t)r * 512 + rem] = v;
                } else {
                    const int head = rem >> 6;
                    const int d    = rem & 63;
                    float* dst = (c == 1) ? g_q : ((c == 2) ? g_k : g_v);
                    dst[((size_t)(b * 8 + head) * 2048 + s) * 64 + d] = v;
                }
            }
        }
    } else {
        #pragma unroll
        for (int ii = 0; ii < 8; ii++) {
            const int r = row0 + ty * 8 + ii;
            #pragma unroll
            for (int jj4 = 0; jj4 < 2; jj4++) {
                const int j = col0 + tx * 8 + jj4 * 4;
                float4 o;
                o.x = acc[ii][jj4 * 4 + 0] + bias[j + 0];
                o.y = acc[ii][jj4 * 4 + 1] + bias[j + 1];
                o.z = acc[ii][jj4 * 4 + 2] + bias[j + 2];
                o.w = acc[ii][jj4 * 4 + 3] + bias[j + 3];
                *(float4*)&out[(size_t)r * 512 + j] = o;
            }
        }
    }
}

// ---------------------------------------------------------------------------
// Causal HSTU attention: o[s] = sum_{t<=s} silu(q[s].k[t] * scale) v[t]
// One block per (64-query tile, b*h). 64x64 key tiles.
// Q/K stored dim-major in smem (float4 fragment reads for both GEMMs).
// ---------------------------------------------------------------------------
#define AST 68   // padded smem row stride (floats), multiple of 4 for float4

__global__ void __launch_bounds__(256) attn_kernel() {
    extern __shared__ float sm[];
    float* Qt = sm;                 // [64][AST]  Qt[d][qi]
    float* Kt = sm + 64 * AST;      // [64][AST]  Kt[d][ki]
    float* Vs = sm + 2 * 64 * AST;  // [64][AST]  Vs[ki][d]
    float* St = sm + 3 * 64 * AST;  // [64][AST]  St[ki][qi]

    const int tid = threadIdx.x;
    const int tx  = tid & 15;       // key / dim direction (4 elems)
    const int ty  = tid >> 4;       // query direction (4 elems)
    const int qt  = blockIdx.x;     // query tile 0..31
    const int bh  = blockIdx.y;     // 0..31
    const int b   = bh >> 3;
    const int h   = bh & 7;
    const size_t base = (size_t)bh * SS * HD;
    const float* qp = g_q + base;
    const float* kp = g_k + base;
    const float* vp = g_v + base;
    const int s0 = qt * 64;

    // Load Q tile transposed (dim-major)
    #pragma unroll
    for (int l = 0; l < 4; l++) {
        int idx = tid + l * 256;
        int r   = idx >> 4;            // 0..63 (query row)
        int f4  = (idx & 15) << 2;     // dim base
        float4 qv = *(const float4*)&qp[(size_t)(s0 + r) * 64 + f4];
        Qt[(f4 + 0) * AST + r] = qv.x;
        Qt[(f4 + 1) * AST + r] = qv.y;
        Qt[(f4 + 2) * AST + r] = qv.z;
        Qt[(f4 + 3) * AST + r] = qv.w;
    }

    float oacc[4][4];
    #pragma unroll
    for (int i = 0; i < 4; i++)
        #pragma unroll
        for (int j = 0; j < 4; j++) oacc[i][j] = 0.0f;

    for (int kt = 0; kt <= qt; kt++) {
        const int t0 = kt * 64;
        __syncthreads();   // prev-iter St/Vs reads done; also orders Qt stores (iter 0)

        // Load K (transposed, dim-major) and V (natural)
        #pragma unroll
        for (int l = 0; l < 4; l++) {
            int idx = tid + l * 256;
            int r   = idx >> 4;
            int f4  = (idx & 15) << 2;
            float4 kv = *(const float4*)&kp[(size_t)(t0 + r) * 64 + f4];
            Kt[(f4 + 0) * AST + r] = kv.x;
            Kt[(f4 + 1) * AST + r] = kv.y;
            Kt[(f4 + 2) * AST + r] = kv.z;
            Kt[(f4 + 3) * AST + r] = kv.w;
            float4 vv = *(const float4*)&vp[(size_t)(t0 + r) * 64 + f4];
            *(float4*)&Vs[r * AST + f4] = vv;
        }
        __syncthreads();

        // scores: S[i][j] = sum_d Q[i][d] * K[j][d]
        float sacc[4][4];
        #pragma unroll
        for (int i = 0; i < 4; i++)
            #pragma unroll
            for (int j = 0; j < 4; j++) sacc[i][j] = 0.0f;

        #pragma unroll 8
        for (int kk = 0; kk < 64; kk++) {
            float qa[4], ka[4];
            *(float4*)qa = *(const float4*)&Qt[kk * AST + ty * 4];
            *(float4*)ka = *(const float4*)&Kt[kk * AST + tx * 4];
            #pragma unroll
            for (int i = 0; i < 4; i++)
                #pragma unroll
                for (int j = 0; j < 4; j++)
                    sacc[i][j] += qa[i] * ka[j];
        }

        // silu + causal mask, store transposed: St[key][query]
        #pragma unroll
        for (int jj = 0; jj < 4; jj++) {
            const int key = t0 + tx * 4 + jj;
            float sv[4];
            #pragma unroll
            for (int ii = 0; ii < 4; ii++) {
                const int qrow = s0 + ty * 4 + ii;
                float v = sacc[ii][jj] * 0.125f;   // 1/sqrt(64)
                v = v / (1.0f + __expf(-v));
                sv[ii] = (key <= qrow) ? v : 0.0f;
            }
            *(float4*)&St[(tx * 4 + jj) * AST + ty * 4] = *(float4*)sv;
        }
        __syncthreads();

        // o[i][d] += sum_t St[t][i] * Vs[t][d]
        #pragma unroll 8
        for (int t = 0; t < 64; t++) {
            float sa[4], va[4];
            *(float4*)sa = *(const float4*)&St[t * AST + ty * 4];
            *(float4*)va = *(const float4*)&Vs[t * AST + tx * 4];
            #pragma unroll
            for (int i = 0; i < 4; i++)
                #pragma unroll
                for (int j = 0; j < 4; j++)
                    oacc[i][j] += sa[i] * va[j];
        }
    }

    // Write o directly in [b, s, h*64+d] layout
    #pragma unroll
    for (int ii = 0; ii < 4; ii++) {
        const int srow = s0 + ty * 4 + ii;
        float4 ov = make_float4(oacc[ii][0], oacc[ii][1], oacc[ii][2], oacc[ii][3]);
        *(float4*)&g_o[((size_t)(b * SS + srow)) * DD + h * 64 + tx * 4] = ov;
    }
}

// ---------------------------------------------------------------------------
// LayerNorm(o) * gate  -> g_ng. One block per row (512 floats), 128 threads.
// Two-pass (mean, then sum((x-m)^2)) for numerical robustness.
// ---------------------------------------------------------------------------
__global__ void __launch_bounds__(128) ln_gate_kernel(
    const float* __restrict__ lng, const float* __restrict__ lnb)
{
    const int row = blockIdx.x;
    const int tid = threadIdx.x;
    const float* op = g_o + (size_t)row * DD;

    float4 x = *(const float4*)&op[tid * 4];
    float s = x.x + x.y + x.z + x.w;

    const int lane = tid & 31, wid = tid >> 5;
    __shared__ float r1[4], r2[4];

    #pragma unroll
    for (int off = 16; off; off >>= 1) s += __shfl_xor_sync(0xffffffffu, s, off);
    if (lane == 0) r1[wid] = s;
    __syncthreads();
    const float m = (r1[0] + r1[1] + r1[2] + r1[3]) * (1.0f / 512.0f);

    const float dx = x.x - m, dy = x.y - m, dz = x.z - m, dw = x.w - m;
    float sq = dx * dx + dy * dy + dz * dz + dw * dw;
    #pragma unroll
    for (int off = 16; off; off >>= 1) sq += __shfl_xor_sync(0xffffffffu, sq, off);
    if (lane == 0) r2[wid] = sq;
    __syncthreads();
    const float var = (r2[0] + r2[1] + r2[2] + r2[3]) * (1.0f / 512.0f);
    const float inv = rsqrtf(var + 1e-5f);

    float4 gv = *(const float4*)&lng[tid * 4];
    float4 bv = *(const float4*)&lnb[tid * 4];
    float4 gg = *(const float4*)&g_gate[(size_t)row * DD + tid * 4];
    float4 o;
    o.x = (dx * inv * gv.x + bv.x) * gg.x;
    o.y = (dy * inv * gv.y + bv.y) * gg.y;
    o.z = (dz * inv * gv.z + bv.z) * gg.z;
    o.w = (dw * inv * gv.w + bv.w) * gg.w;
    *(float4*)&g_ng[(size_t)row * DD + tid * 4] = o;
}

// ---------------------------------------------------------------------------
extern "C" void kernel_launch(void* const* d_in, const int* in_sizes, int n_in,
                              void* d_out, int out_size) {
    const float* x   = (const float*)d_in[0];
    const float* W1  = (const float*)d_in[1];
    const float* b1  = (const float*)d_in[2];
    const float* lng = (const float*)d_in[3];
    const float* lnb = (const float*)d_in[4];
    const float* W2  = (const float*)d_in[5];
    const float* b2  = (const float*)d_in[6];
    float* out = (float*)d_out;

    const int attn_smem = 4 * 64 * AST * (int)sizeof(float);  // 69632 B
    cudaFuncSetAttribute(attn_kernel, cudaFuncAttributeMaxDynamicSharedMemorySize,
                         attn_smem);

    // 1) h = silu(x @ W1^T + b1), scattered to gate/q/k/v
    gemm_kernel<0><<<dim3(2048 / 128, MROWS / 128), 256>>>(x, W1, b1, out);

    // 2) causal silu-attention -> g_o [b,s,d]
    attn_kernel<<<dim3(SS / 64, BB * HH), 256, attn_smem>>>();

    // 3) layernorm(o) * gate -> g_ng
    ln_gate_kernel<<<MROWS, 128>>>(lng, lnb);

    // 4) out = g_ng @ W2^T + b2
    gemm_kernel<1><<<dim3(512 / 128, MROWS / 128), 256>>>(nullptr, W2, b2, out);
}

// round 9
// speedup vs baseline: 1.3846x; 1.3846x over previous
#include <cuda_runtime.h>
#include <cstdint>

// Problem constants
#define BB 4
#define SS 2048
#define DD 512
#define HH 8
#define HD 64
#define MROWS (BB*SS)   // 8192

// Scratch (static device arrays -- allocation-free per harness rules)
__device__ float g_gate[BB*SS*DD];       // [b,s,d]
__device__ float g_q[BB*HH*SS*HD];       // [b,h,s,d]
__device__ float g_k[BB*HH*SS*HD];
__device__ float g_v[BB*HH*SS*HD];
__device__ float g_o[BB*SS*DD];          // [b,s,d]
__device__ float g_ng[BB*SS*DD];         // layernorm(o) * gate

__device__ __forceinline__ float silu_f(float x) {
    return x / (1.0f + __expf(-x));
}
__device__ __forceinline__ uint32_t f2tf(float x) {
    uint32_t r; asm("cvt.rna.tf32.f32 %0, %1;" : "=r"(r) : "f"(x)); return r;
}
// D = A(16x8,row) * B(8x8,col) + D, tf32 in, f32 accum
__device__ __forceinline__ void mma_tf32(float* c, const uint32_t* a, const uint32_t* b) {
    asm volatile(
        "mma.sync.aligned.m16n8k8.row.col.f32.tf32.tf32.f32 "
        "{%0,%1,%2,%3}, {%4,%5,%6,%7}, {%8,%9}, {%0,%1,%2,%3};"
        : "+f"(c[0]), "+f"(c[1]), "+f"(c[2]), "+f"(c[3])
        : "r"(a[0]), "r"(a[1]), "r"(a[2]), "r"(a[3]), "r"(b[0]), "r"(b[1]));
}

// ---------------------------------------------------------------------------
// tf32 mma.sync GEMM: C[M,N] = A[M,512] @ W[N,512]^T (+bias, +epilogue)
// CTA: 128x128 tile, 256 threads = 8 warps (2 M x 4 N), warp = 64x32,
// per warp 4x4 tiles of m16n8k8. BK=32 smem staging, row stride 36 words
// (36 mod 32 = 4 -> fragment loads across a warp hit 32 distinct banks).
// MODE 0: A = x,    epilogue = silu(.)+scatter to gate/q/k/v  (N = 2048)
// MODE 1: A = g_ng, epilogue = +b2 -> out                     (N = 512)
// ---------------------------------------------------------------------------
#define KST 36
template<int MODE>
__global__ void __launch_bounds__(256) tc_gemm(
    const float* __restrict__ A_in,
    const float* __restrict__ W,
    const float* __restrict__ bias,
    float* __restrict__ out)
{
    __shared__ uint32_t As[128][KST];   // [m][k] tf32 bits
    __shared__ uint32_t Bs[128][KST];   // [n][k] tf32 bits

    const float* A = (MODE == 0) ? A_in : g_ng;
    const int tid  = threadIdx.x;
    const int wid  = tid >> 5;
    const int lane = tid & 31;
    const int g    = lane >> 2;        // fragment group (row)
    const int t    = lane & 3;         // thread-in-group (col)
    const int row0 = blockIdx.y * 128;
    const int col0 = blockIdx.x * 128;
    const int wm   = (wid >> 2) * 64;  // warp M offset within tile
    const int wn   = (wid & 3) * 32;   // warp N offset within tile

    float acc[4][4][4];
    #pragma unroll
    for (int i = 0; i < 4; i++)
        #pragma unroll
        for (int j = 0; j < 4; j++)
            #pragma unroll
            for (int q = 0; q < 4; q++) acc[i][j][q] = 0.0f;

    for (int kb = 0; kb < 16; kb++) {
        const int k0 = kb * 32;
        // stage A,B 128x32 f32 -> tf32 smem. 1024 float4 per tile, 4/thread.
        #pragma unroll
        for (int l = 0; l < 4; l++) {
            const int idx = tid + l * 256;
            const int r   = idx >> 3;
            const int c4  = (idx & 7) << 2;
            float4 av = *(const float4*)&A[(size_t)(row0 + r) * 512 + k0 + c4];
            *(uint4*)&As[r][c4] = make_uint4(f2tf(av.x), f2tf(av.y), f2tf(av.z), f2tf(av.w));
            float4 bv = *(const float4*)&W[(size_t)(col0 + r) * 512 + k0 + c4];
            *(uint4*)&Bs[r][c4] = make_uint4(f2tf(bv.x), f2tf(bv.y), f2tf(bv.z), f2tf(bv.w));
        }
        __syncthreads();

        #pragma unroll
        for (int k8 = 0; k8 < 4; k8++) {
            const int kk = k8 * 8;
            uint32_t af[4][4];
            #pragma unroll
            for (int mt = 0; mt < 4; mt++) {
                const int mr = wm + mt * 16 + g;
                af[mt][0] = As[mr    ][kk + t];
                af[mt][1] = As[mr + 8][kk + t];
                af[mt][2] = As[mr    ][kk + t + 4];
                af[mt][3] = As[mr + 8][kk + t + 4];
            }
            uint32_t bf[4][2];
            #pragma unroll
            for (int nt = 0; nt < 4; nt++) {
                const int nr = wn + nt * 8 + g;
                bf[nt][0] = Bs[nr][kk + t];
                bf[nt][1] = Bs[nr][kk + t + 4];
            }
            #pragma unroll
            for (int mt = 0; mt < 4; mt++)
                #pragma unroll
                for (int nt = 0; nt < 4; nt++)
                    mma_tf32(acc[mt][nt], af[mt], bf[nt]);
        }
        __syncthreads();
    }

    // Epilogue. Accumulator frag: c0,c1 -> (row g, cols 2t,2t+1); c2,c3 -> row g+8.
    #pragma unroll
    for (int mt = 0; mt < 4; mt++) {
        #pragma unroll
        for (int half = 0; half < 2; half++) {
            const int r = row0 + wm + mt * 16 + g + half * 8;
            const int b = r >> 11;
            const int s = r & 2047;
            #pragma unroll
            for (int nt = 0; nt < 4; nt++) {
                const int j = col0 + wn + nt * 8 + 2 * t;
                float2 v;
                v.x = acc[mt][nt][half * 2 + 0] + __ldg(&bias[j]);
                v.y = acc[mt][nt][half * 2 + 1] + __ldg(&bias[j + 1]);
                if (MODE == 0) {
                    v.x = silu_f(v.x);
                    v.y = silu_f(v.y);
                    // scatter: j = c*512 + head*64 + d (c: 0=gate,1=q,2=k,3=v)
                    const int c   = j >> 9;
                    const int rem = j & 511;
                    if (c == 0) {
                        *(float2*)&g_gate[(size_t)r * 512 + rem] = v;
                    } else {
                        const int head = rem >> 6;
                        const int d    = rem & 63;
                        float* dst = (c == 1) ? g_q : ((c == 2) ? g_k : g_v);
                        *(float2*)&dst[((size_t)(b * 8 + head) * 2048 + s) * 64 + d] = v;
                    }
                } else {
                    *(float2*)&out[(size_t)r * 512 + j] = v;
                }
            }
        }
    }
}

// ---------------------------------------------------------------------------
// Causal HSTU attention (fp32 FFMA, unchanged known-good path)
// ---------------------------------------------------------------------------
#define AST 68

__global__ void __launch_bounds__(256) attn_kernel() {
    extern __shared__ float sm[];
    float* Qt = sm;                 // [64][AST]  Qt[d][qi]
    float* Kt = sm + 64 * AST;      // [64][AST]  Kt[d][ki]
    float* Vs = sm + 2 * 64 * AST;  // [64][AST]  Vs[ki][d]
    float* St = sm + 3 * 64 * AST;  // [64][AST]  St[ki][qi]

    const int tid = threadIdx.x;
    const int tx  = tid & 15;
    const int ty  = tid >> 4;
    const int qt  = blockIdx.x;
    const int bh  = blockIdx.y;
    const int b   = bh >> 3;
    const int h   = bh & 7;
    const size_t base = (size_t)bh * SS * HD;
    const float* qp = g_q + base;
    const float* kp = g_k + base;
    const float* vp = g_v + base;
    const int s0 = qt * 64;

    #pragma unroll
    for (int l = 0; l < 4; l++) {
        int idx = tid + l * 256;
        int r   = idx >> 4;
        int f4  = (idx & 15) << 2;
        float4 qv = *(const float4*)&qp[(size_t)(s0 + r) * 64 + f4];
        Qt[(f4 + 0) * AST + r] = qv.x;
        Qt[(f4 + 1) * AST + r] = qv.y;
        Qt[(f4 + 2) * AST + r] = qv.z;
        Qt[(f4 + 3) * AST + r] = qv.w;
    }

    float oacc[4][4];
    #pragma unroll
    for (int i = 0; i < 4; i++)
        #pragma unroll
        for (int j = 0; j < 4; j++) oacc[i][j] = 0.0f;

    for (int kt = 0; kt <= qt; kt++) {
        const int t0 = kt * 64;
        __syncthreads();

        #pragma unroll
        for (int l = 0; l < 4; l++) {
            int idx = tid + l * 256;
            int r   = idx >> 4;
            int f4  = (idx & 15) << 2;
            float4 kv = *(const float4*)&kp[(size_t)(t0 + r) * 64 + f4];
            Kt[(f4 + 0) * AST + r] = kv.x;
            Kt[(f4 + 1) * AST + r] = kv.y;
            Kt[(f4 + 2) * AST + r] = kv.z;
            Kt[(f4 + 3) * AST + r] = kv.w;
            float4 vv = *(const float4*)&vp[(size_t)(t0 + r) * 64 + f4];
            *(float4*)&Vs[r * AST + f4] = vv;
        }
        __syncthreads();

        float sacc[4][4];
        #pragma unroll
        for (int i = 0; i < 4; i++)
            #pragma unroll
            for (int j = 0; j < 4; j++) sacc[i][j] = 0.0f;

        #pragma unroll 8
        for (int kk = 0; kk < 64; kk++) {
            float qa[4], ka[4];
            *(float4*)qa = *(const float4*)&Qt[kk * AST + ty * 4];
            *(float4*)ka = *(const float4*)&Kt[kk * AST + tx * 4];
            #pragma unroll
            for (int i = 0; i < 4; i++)
                #pragma unroll
                for (int j = 0; j < 4; j++)
                    sacc[i][j] += qa[i] * ka[j];
        }

        #pragma unroll
        for (int jj = 0; jj < 4; jj++) {
            const int key = t0 + tx * 4 + jj;
            float sv[4];
            #pragma unroll
            for (int ii = 0; ii < 4; ii++) {
                const int qrow = s0 + ty * 4 + ii;
                float v = sacc[ii][jj] * 0.125f;
                v = v / (1.0f + __expf(-v));
                sv[ii] = (key <= qrow) ? v : 0.0f;
            }
            *(float4*)&St[(tx * 4 + jj) * AST + ty * 4] = *(float4*)sv;
        }
        __syncthreads();

        #pragma unroll 8
        for (int t = 0; t < 64; t++) {
            float sa[4], va[4];
            *(float4*)sa = *(const float4*)&St[t * AST + ty * 4];
            *(float4*)va = *(const float4*)&Vs[t * AST + tx * 4];
            #pragma unroll
            for (int i = 0; i < 4; i++)
                #pragma unroll
                for (int j = 0; j < 4; j++)
                    oacc[i][j] += sa[i] * va[j];
        }
    }

    #pragma unroll
    for (int ii = 0; ii < 4; ii++) {
        const int srow = s0 + ty * 4 + ii;
        float4 ov = make_float4(oacc[ii][0], oacc[ii][1], oacc[ii][2], oacc[ii][3]);
        *(float4*)&g_o[((size_t)(b * SS + srow)) * DD + h * 64 + tx * 4] = ov;
    }
}

// ---------------------------------------------------------------------------
// LayerNorm(o) * gate  -> g_ng
// ---------------------------------------------------------------------------
__global__ void __launch_bounds__(128) ln_gate_kernel(
    const float* __restrict__ lng, const float* __restrict__ lnb)
{
    const int row = blockIdx.x;
    const int tid = threadIdx.x;
    const float* op = g_o + (size_t)row * DD;

    float4 x = *(const float4*)&op[tid * 4];
    float s = x.x + x.y + x.z + x.w;

    const int lane = tid & 31, wid = tid >> 5;
    __shared__ float r1[4], r2[4];

    #pragma unroll
    for (int off = 16; off; off >>= 1) s += __shfl_xor_sync(0xffffffffu, s, off);
    if (lane == 0) r1[wid] = s;
    __syncthreads();
    const float m = (r1[0] + r1[1] + r1[2] + r1[3]) * (1.0f / 512.0f);

    const float dx = x.x - m, dy = x.y - m, dz = x.z - m, dw = x.w - m;
    float sq = dx * dx + dy * dy + dz * dz + dw * dw;
    #pragma unroll
    for (int off = 16; off; off >>= 1) sq += __shfl_xor_sync(0xffffffffu, sq, off);
    if (lane == 0) r2[wid] = sq;
    __syncthreads();
    const float var = (r2[0] + r2[1] + r2[2] + r2[3]) * (1.0f / 512.0f);
    const float inv = rsqrtf(var + 1e-5f);

    float4 gv = *(const float4*)&lng[tid * 4];
    float4 bv = *(const float4*)&lnb[tid * 4];
    float4 gg = *(const float4*)&g_gate[(size_t)row * DD + tid * 4];
    float4 o;
    o.x = (dx * inv * gv.x + bv.x) * gg.x;
    o.y = (dy * inv * gv.y + bv.y) * gg.y;
    o.z = (dz * inv * gv.z + bv.z) * gg.z;
    o.w = (dw * inv * gv.w + bv.w) * gg.w;
    *(float4*)&g_ng[(size_t)row * DD + tid * 4] = o;
}

// ---------------------------------------------------------------------------
extern "C" void kernel_launch(void* const* d_in, const int* in_sizes, int n_in,
                              void* d_out, int out_size) {
    const float* x   = (const float*)d_in[0];
    const float* W1  = (const float*)d_in[1];
    const float* b1  = (const float*)d_in[2];
    const float* lng = (const float*)d_in[3];
    const float* lnb = (const float*)d_in[4];
    const float* W2  = (const float*)d_in[5];
    const float* b2  = (const float*)d_in[6];
    float* out = (float*)d_out;

    const int attn_smem = 4 * 64 * AST * (int)sizeof(float);  // 69632 B
    cudaFuncSetAttribute(attn_kernel, cudaFuncAttributeMaxDynamicSharedMemorySize,
                         attn_smem);

    // 1) h = silu(x @ W1^T + b1), scattered to gate/q/k/v   (tf32 mma.sync)
    tc_gemm<0><<<dim3(2048 / 128, MROWS / 128), 256>>>(x, W1, b1, out);

    // 2) causal silu-attention -> g_o [b,s,d]               (fp32 FFMA)
    attn_kernel<<<dim3(SS / 64, BB * HH), 256, attn_smem>>>();

    // 3) layernorm(o) * gate -> g_ng
    ln_gate_kernel<<<MROWS, 128>>>(lng, lnb);

    // 4) out = g_ng @ W2^T + b2                             (tf32 mma.sync)
    tc_gemm<1><<<dim3(512 / 128, MROWS / 128), 256>>>(nullptr, W2, b2, out);
}

// round 10
// speedup vs baseline: 2.3440x; 1.6929x over previous
#include <cuda_runtime.h>
#include <cstdint>

// Problem constants
#define BB 4
#define SS 2048
#define DD 512
#define HH 8
#define HD 64
#define MROWS (BB*SS)   // 8192

// Scratch (static device arrays -- allocation-free per harness rules)
__device__ float g_gate[BB*SS*DD];       // [b,s,d]
__device__ float g_q[BB*HH*SS*HD];       // [b,h,s,d]
__device__ float g_k[BB*HH*SS*HD];
__device__ float g_v[BB*HH*SS*HD];
__device__ float g_o[BB*SS*DD];          // [b,s,d]
__device__ float g_ng[BB*SS*DD];         // layernorm(o) * gate

__device__ __forceinline__ float silu_f(float x) {
    return x / (1.0f + __expf(-x));
}
__device__ __forceinline__ uint32_t f2tf(float x) {
    uint32_t r; asm("cvt.rna.tf32.f32 %0, %1;" : "=r"(r) : "f"(x)); return r;
}
// D = A(16x8,row) * B(8x8,col) + D, tf32 in, f32 accum
__device__ __forceinline__ void mma_tf32(float* c, const uint32_t* a, const uint32_t* b) {
    asm volatile(
        "mma.sync.aligned.m16n8k8.row.col.f32.tf32.tf32.f32 "
        "{%0,%1,%2,%3}, {%4,%5,%6,%7}, {%8,%9}, {%0,%1,%2,%3};"
        : "+f"(c[0]), "+f"(c[1]), "+f"(c[2]), "+f"(c[3])
        : "r"(a[0]), "r"(a[1]), "r"(a[2]), "r"(a[3]), "r"(b[0]), "r"(b[1]));
}

// ---------------------------------------------------------------------------
// tf32 mma.sync GEMM: C[M,N] = A[M,512] @ W[N,512]^T (+bias, +epilogue)
// CTA: 128x128 tile, 256 threads = 8 warps (2 M x 4 N), warp = 64x32.
// MODE 0: A = x,    epilogue = silu(.)+scatter to gate/q/k/v  (N = 2048)
// MODE 1: A = g_ng, epilogue = +b2 -> out                     (N = 512)
// ---------------------------------------------------------------------------
#define KST 36
template<int MODE>
__global__ void __launch_bounds__(256) tc_gemm(
    const float* __restrict__ A_in,
    const float* __restrict__ W,
    const float* __restrict__ bias,
    float* __restrict__ out)
{
    __shared__ uint32_t As[128][KST];   // [m][k] tf32 bits
    __shared__ uint32_t Bs[128][KST];   // [n][k] tf32 bits

    const float* A = (MODE == 0) ? A_in : g_ng;
    const int tid  = threadIdx.x;
    const int wid  = tid >> 5;
    const int lane = tid & 31;
    const int g    = lane >> 2;
    const int t    = lane & 3;
    const int row0 = blockIdx.y * 128;
    const int col0 = blockIdx.x * 128;
    const int wm   = (wid >> 2) * 64;
    const int wn   = (wid & 3) * 32;

    float acc[4][4][4];
    #pragma unroll
    for (int i = 0; i < 4; i++)
        #pragma unroll
        for (int j = 0; j < 4; j++)
            #pragma unroll
            for (int q = 0; q < 4; q++) acc[i][j][q] = 0.0f;

    for (int kb = 0; kb < 16; kb++) {
        const int k0 = kb * 32;
        #pragma unroll
        for (int l = 0; l < 4; l++) {
            const int idx = tid + l * 256;
            const int r   = idx >> 3;
            const int c4  = (idx & 7) << 2;
            float4 av = *(const float4*)&A[(size_t)(row0 + r) * 512 + k0 + c4];
            *(uint4*)&As[r][c4] = make_uint4(f2tf(av.x), f2tf(av.y), f2tf(av.z), f2tf(av.w));
            float4 bv = *(const float4*)&W[(size_t)(col0 + r) * 512 + k0 + c4];
            *(uint4*)&Bs[r][c4] = make_uint4(f2tf(bv.x), f2tf(bv.y), f2tf(bv.z), f2tf(bv.w));
        }
        __syncthreads();

        #pragma unroll
        for (int k8 = 0; k8 < 4; k8++) {
            const int kk = k8 * 8;
            uint32_t af[4][4];
            #pragma unroll
            for (int mt = 0; mt < 4; mt++) {
                const int mr = wm + mt * 16 + g;
                af[mt][0] = As[mr    ][kk + t];
                af[mt][1] = As[mr + 8][kk + t];
                af[mt][2] = As[mr    ][kk + t + 4];
                af[mt][3] = As[mr + 8][kk + t + 4];
            }
            uint32_t bf[4][2];
            #pragma unroll
            for (int nt = 0; nt < 4; nt++) {
                const int nr = wn + nt * 8 + g;
                bf[nt][0] = Bs[nr][kk + t];
                bf[nt][1] = Bs[nr][kk + t + 4];
            }
            #pragma unroll
            for (int mt = 0; mt < 4; mt++)
                #pragma unroll
                for (int nt = 0; nt < 4; nt++)
                    mma_tf32(acc[mt][nt], af[mt], bf[nt]);
        }
        __syncthreads();
    }

    #pragma unroll
    for (int mt = 0; mt < 4; mt++) {
        #pragma unroll
        for (int half = 0; half < 2; half++) {
            const int r = row0 + wm + mt * 16 + g + half * 8;
            const int b = r >> 11;
            const int s = r & 2047;
            #pragma unroll
            for (int nt = 0; nt < 4; nt++) {
                const int j = col0 + wn + nt * 8 + 2 * t;
                float2 v;
                v.x = acc[mt][nt][half * 2 + 0] + __ldg(&bias[j]);
                v.y = acc[mt][nt][half * 2 + 1] + __ldg(&bias[j + 1]);
                if (MODE == 0) {
                    v.x = silu_f(v.x);
                    v.y = silu_f(v.y);
                    const int c   = j >> 9;
                    const int rem = j & 511;
                    if (c == 0) {
                        *(float2*)&g_gate[(size_t)r * 512 + rem] = v;
                    } else {
                        const int head = rem >> 6;
                        const int d    = rem & 63;
                        float* dst = (c == 1) ? g_q : ((c == 2) ? g_k : g_v);
                        *(float2*)&dst[((size_t)(b * 8 + head) * 2048 + s) * 64 + d] = v;
                    }
                } else {
                    *(float2*)&out[(size_t)r * 512 + j] = v;
                }
            }
        }
    }
}

// ---------------------------------------------------------------------------
// Causal HSTU attention on tf32 mma.sync.
// Block: 256 thr = 8 warps (4 M-query x 2 N), 64-query tile per block.
// Per key tile (64 keys): S = silu(Q K^T /8) masked -> St (tf32 smem),
// then O += St @ V (V staged transposed as Vt[dim][key] = col-major B).
// Fragment/accumulator layouts identical to tc_gemm (validated).
// ---------------------------------------------------------------------------
#define AQST 68   // smem word stride; 68 mod 32 = 4 -> conflict-free frags

__global__ void __launch_bounds__(256) attn_mma_kernel() {
    extern __shared__ uint32_t smw[];
    uint32_t* Qs = smw;                 // [64][AQST] tf32 [query][dim]
    uint32_t* Ks = smw + 64 * AQST;     // [64][AQST] tf32 [key][dim]
    uint32_t* Vt = smw + 2 * 64 * AQST; // [64][AQST] tf32 [dim][key]
    uint32_t* St = smw + 3 * 64 * AQST; // [64][AQST] tf32 [query][key]

    const int tid  = threadIdx.x;
    const int wid  = tid >> 5;
    const int lane = tid & 31;
    const int g    = lane >> 2;
    const int t    = lane & 3;
    const int qt   = blockIdx.x;
    const int bh   = blockIdx.y;
    const int b    = bh >> 3;
    const int h    = bh & 7;
    const size_t base = (size_t)bh * SS * HD;
    const float* qp = g_q + base;
    const float* kp = g_k + base;
    const float* vp = g_v + base;
    const int s0 = qt * 64;
    const int wm = (wid >> 1) * 16;   // query offset: 0,16,32,48
    const int wn = (wid & 1) * 32;    // key/dim offset: 0,32

    // Stage Q (tf32)
    #pragma unroll
    for (int l = 0; l < 4; l++) {
        const int idx = tid + l * 256;
        const int r   = idx >> 4;
        const int c4  = (idx & 15) << 2;
        float4 qv = *(const float4*)&qp[(size_t)(s0 + r) * 64 + c4];
        *(uint4*)&Qs[r * AQST + c4] =
            make_uint4(f2tf(qv.x), f2tf(qv.y), f2tf(qv.z), f2tf(qv.w));
    }

    float oacc[4][4];
    #pragma unroll
    for (int i = 0; i < 4; i++)
        #pragma unroll
        for (int j = 0; j < 4; j++) oacc[i][j] = 0.0f;

    for (int kt = 0; kt <= qt; kt++) {
        const int t0 = kt * 64;
        __syncthreads();   // protect Ks/Vt/St still being read (and Qs, iter 0)

        // Stage K (tf32, [key][dim]) and V transposed (tf32, [dim][key])
        #pragma unroll
        for (int l = 0; l < 4; l++) {
            const int idx = tid + l * 256;
            const int r   = idx >> 4;
            const int c4  = (idx & 15) << 2;
            float4 kv = *(const float4*)&kp[(size_t)(t0 + r) * 64 + c4];
            *(uint4*)&Ks[r * AQST + c4] =
                make_uint4(f2tf(kv.x), f2tf(kv.y), f2tf(kv.z), f2tf(kv.w));
            float4 vv = *(const float4*)&vp[(size_t)(t0 + r) * 64 + c4];
            Vt[(c4 + 0) * AQST + r] = f2tf(vv.x);
            Vt[(c4 + 1) * AQST + r] = f2tf(vv.y);
            Vt[(c4 + 2) * AQST + r] = f2tf(vv.z);
            Vt[(c4 + 3) * AQST + r] = f2tf(vv.w);
        }
        __syncthreads();

        // ---- GEMM 1: scores = Q @ K^T  (M=16 queries, N=32 keys per warp)
        float sacc[4][4];
        #pragma unroll
        for (int i = 0; i < 4; i++)
            #pragma unroll
            for (int j = 0; j < 4; j++) sacc[i][j] = 0.0f;

        #pragma unroll
        for (int k8 = 0; k8 < 8; k8++) {
            const int kk = k8 * 8;
            uint32_t af[4];
            const int mr = wm + g;
            af[0] = Qs[mr * AQST + kk + t];
            af[1] = Qs[(mr + 8) * AQST + kk + t];
            af[2] = Qs[mr * AQST + kk + t + 4];
            af[3] = Qs[(mr + 8) * AQST + kk + t + 4];
            uint32_t bf[4][2];
            #pragma unroll
            for (int nt = 0; nt < 4; nt++) {
                const int nr = wn + nt * 8 + g;
                bf[nt][0] = Ks[nr * AQST + kk + t];
                bf[nt][1] = Ks[nr * AQST + kk + t + 4];
            }
            #pragma unroll
            for (int nt = 0; nt < 4; nt++)
                mma_tf32(sacc[nt], af, bf[nt]);
        }

        // silu + causal mask on fragments, re-round to tf32 into St
        const bool diag = (kt == qt);
        #pragma unroll
        for (int nt = 0; nt < 4; nt++) {
            const int klocal = wn + nt * 8 + 2 * t;
            const int key    = t0 + klocal;
            #pragma unroll
            for (int half = 0; half < 2; half++) {
                const int qlocal = wm + g + half * 8;
                const int qrow   = s0 + qlocal;
                float v0 = sacc[nt][half * 2 + 0] * 0.125f;
                float v1 = sacc[nt][half * 2 + 1] * 0.125f;
                v0 = silu_f(v0);
                v1 = silu_f(v1);
                if (diag) {
                    if (key     > qrow) v0 = 0.0f;
                    if (key + 1 > qrow) v1 = 0.0f;
                }
                *(uint2*)&St[qlocal * AQST + klocal] = make_uint2(f2tf(v0), f2tf(v1));
            }
        }
        __syncthreads();

        // ---- GEMM 2: O += St @ V  (A=St [query][key], B=Vt [dim][key])
        #pragma unroll
        for (int k8 = 0; k8 < 8; k8++) {
            const int kk = k8 * 8;
            uint32_t af[4];
            const int mr = wm + g;
            af[0] = St[mr * AQST + kk + t];
            af[1] = St[(mr + 8) * AQST + kk + t];
            af[2] = St[mr * AQST + kk + t + 4];
            af[3] = St[(mr + 8) * AQST + kk + t + 4];
            uint32_t bf[4][2];
            #pragma unroll
            for (int nt = 0; nt < 4; nt++) {
                const int nr = wn + nt * 8 + g;
                bf[nt][0] = Vt[nr * AQST + kk + t];
                bf[nt][1] = Vt[nr * AQST + kk + t + 4];
            }
            #pragma unroll
            for (int nt = 0; nt < 4; nt++)
                mma_tf32(oacc[nt], af, bf[nt]);
        }
    }

    // Write O in [b, s, h*64+dim] layout
    #pragma unroll
    for (int nt = 0; nt < 4; nt++) {
        const int dim = wn + nt * 8 + 2 * t;
        #pragma unroll
        for (int half = 0; half < 2; half++) {
            const int srow = s0 + wm + g + half * 8;
            float2 ov = make_float2(oacc[nt][half * 2 + 0], oacc[nt][half * 2 + 1]);
            *(float2*)&g_o[((size_t)(b * SS + srow)) * DD + h * 64 + dim] = ov;
        }
    }
}

// ---------------------------------------------------------------------------
// LayerNorm(o) * gate  -> g_ng
// ---------------------------------------------------------------------------
__global__ void __launch_bounds__(128) ln_gate_kernel(
    const float* __restrict__ lng, const float* __restrict__ lnb)
{
    const int row = blockIdx.x;
    const int tid = threadIdx.x;
    const float* op = g_o + (size_t)row * DD;

    float4 x = *(const float4*)&op[tid * 4];
    float s = x.x + x.y + x.z + x.w;

    const int lane = tid & 31, wid = tid >> 5;
    __shared__ float r1[4], r2[4];

    #pragma unroll
    for (int off = 16; off; off >>= 1) s += __shfl_xor_sync(0xffffffffu, s, off);
    if (lane == 0) r1[wid] = s;
    __syncthreads();
    const float m = (r1[0] + r1[1] + r1[2] + r1[3]) * (1.0f / 512.0f);

    const float dx = x.x - m, dy = x.y - m, dz = x.z - m, dw = x.w - m;
    float sq = dx * dx + dy * dy + dz * dz + dw * dw;
    #pragma unroll
    for (int off = 16; off; off >>= 1) sq += __shfl_xor_sync(0xffffffffu, sq, off);
    if (lane == 0) r2[wid] = sq;
    __syncthreads();
    const float var = (r2[0] + r2[1] + r2[2] + r2[3]) * (1.0f / 512.0f);
    const float inv = rsqrtf(var + 1e-5f);

    float4 gv = *(const float4*)&lng[tid * 4];
    float4 bv = *(const float4*)&lnb[tid * 4];
    float4 gg = *(const float4*)&g_gate[(size_t)row * DD + tid * 4];
    float4 o;
    o.x = (dx * inv * gv.x + bv.x) * gg.x;
    o.y = (dy * inv * gv.y + bv.y) * gg.y;
    o.z = (dz * inv * gv.z + bv.z) * gg.z;
    o.w = (dw * inv * gv.w + bv.w) * gg.w;
    *(float4*)&g_ng[(size_t)row * DD + tid * 4] = o;
}

// ---------------------------------------------------------------------------
extern "C" void kernel_launch(void* const* d_in, const int* in_sizes, int n_in,
                              void* d_out, int out_size) {
    const float* x   = (const float*)d_in[0];
    const float* W1  = (const float*)d_in[1];
    const float* b1  = (const float*)d_in[2];
    const float* lng = (const float*)d_in[3];
    const float* lnb = (const float*)d_in[4];
    const float* W2  = (const float*)d_in[5];
    const float* b2  = (const float*)d_in[6];
    float* out = (float*)d_out;

    const int attn_smem = 4 * 64 * AQST * (int)sizeof(uint32_t);  // 69632 B
    cudaFuncSetAttribute(attn_mma_kernel,
                         cudaFuncAttributeMaxDynamicSharedMemorySize, attn_smem);

    // 1) h = silu(x @ W1^T + b1), scattered to gate/q/k/v   (tf32 mma.sync)
    tc_gemm<0><<<dim3(2048 / 128, MROWS / 128), 256>>>(x, W1, b1, out);

    // 2) causal silu-attention -> g_o [b,s,d]               (tf32 mma.sync)
    attn_mma_kernel<<<dim3(SS / 64, BB * HH), 256, attn_smem>>>();

    // 3) layernorm(o) * gate -> g_ng
    ln_gate_kernel<<<MROWS, 128>>>(lng, lnb);

    // 4) out = g_ng @ W2^T + b2                             (tf32 mma.sync)
    tc_gemm<1><<<dim3(512 / 128, MROWS / 128), 256>>>(nullptr, W2, b2, out);
}

// round 11
// speedup vs baseline: 2.9594x; 1.2625x over previous
#include <cuda_runtime.h>
#include <cstdint>

// Problem constants
#define BB 4
#define SS 2048
#define DD 512
#define HH 8
#define HD 64
#define MROWS (BB*SS)   // 8192

// Scratch (static device arrays -- allocation-free per harness rules)
__device__ float g_gate[BB*SS*DD];       // [b,s,d]
__device__ float g_q[BB*HH*SS*HD];       // [b,h,s,d]
__device__ float g_k[BB*HH*SS*HD];
__device__ float g_v[BB*HH*SS*HD];
__device__ float g_o[BB*SS*DD];          // [b,s,d]
__device__ float g_ng[BB*SS*DD];         // layernorm(o) * gate

__device__ __forceinline__ float silu_f(float x) {
    return __fdividef(x, 1.0f + __expf(-x));
}
__device__ __forceinline__ uint32_t f2tf(float x) {
    uint32_t r; asm("cvt.rna.tf32.f32 %0, %1;" : "=r"(r) : "f"(x)); return r;
}
// D = A(16x8,row) * B(8x8,col) + D, tf32 in, f32 accum
__device__ __forceinline__ void mma_tf32(float* c, const uint32_t* a, const uint32_t* b) {
    asm volatile(
        "mma.sync.aligned.m16n8k8.row.col.f32.tf32.tf32.f32 "
        "{%0,%1,%2,%3}, {%4,%5,%6,%7}, {%8,%9}, {%0,%1,%2,%3};"
        : "+f"(c[0]), "+f"(c[1]), "+f"(c[2]), "+f"(c[3])
        : "r"(a[0]), "r"(a[1]), "r"(a[2]), "r"(a[3]), "r"(b[0]), "r"(b[1]));
}

// ---------------------------------------------------------------------------
// tf32 mma.sync GEMM: C[M,N] = A[M,512] @ W[N,512]^T (+bias, +epilogue)
// CTA: 128x128 tile, 256 threads = 8 warps (2 M x 4 N), warp = 64x32.
// Register prefetch of the next K-block overlaps LDG latency with MMA.
// MODE 0: A = x,    epilogue = silu(.)+scatter to gate/q/k/v  (N = 2048)
// MODE 1: A = g_ng, epilogue = +b2 -> out                     (N = 512)
// ---------------------------------------------------------------------------
#define KST 36
template<int MODE>
__global__ void __launch_bounds__(256) tc_gemm(
    const float* __restrict__ A_in,
    const float* __restrict__ W,
    const float* __restrict__ bias,
    float* __restrict__ out)
{
    __shared__ uint32_t As[128][KST];   // [m][k] tf32 bits
    __shared__ uint32_t Bs[128][KST];   // [n][k] tf32 bits

    const float* A = (MODE == 0) ? A_in : g_ng;
    const int tid  = threadIdx.x;
    const int wid  = tid >> 5;
    const int lane = tid & 31;
    const int g    = lane >> 2;
    const int t    = lane & 3;
    const int row0 = blockIdx.y * 128;
    const int col0 = blockIdx.x * 128;
    const int wm   = (wid >> 2) * 64;
    const int wn   = (wid & 3) * 32;

    float acc[4][4][4];
    #pragma unroll
    for (int i = 0; i < 4; i++)
        #pragma unroll
        for (int j = 0; j < 4; j++)
            #pragma unroll
            for (int q = 0; q < 4; q++) acc[i][j][q] = 0.0f;

    // prefetch K-block 0
    float4 pa[4], pb[4];
    #pragma unroll
    for (int l = 0; l < 4; l++) {
        const int idx = tid + l * 256;
        const int r   = idx >> 3;
        const int c4  = (idx & 7) << 2;
        pa[l] = *(const float4*)&A[(size_t)(row0 + r) * 512 + c4];
        pb[l] = *(const float4*)&W[(size_t)(col0 + r) * 512 + c4];
    }

    for (int kb = 0; kb < 16; kb++) {
        // store prefetched block (cvt to tf32)
        #pragma unroll
        for (int l = 0; l < 4; l++) {
            const int idx = tid + l * 256;
            const int r   = idx >> 3;
            const int c4  = (idx & 7) << 2;
            *(uint4*)&As[r][c4] =
                make_uint4(f2tf(pa[l].x), f2tf(pa[l].y), f2tf(pa[l].z), f2tf(pa[l].w));
            *(uint4*)&Bs[r][c4] =
                make_uint4(f2tf(pb[l].x), f2tf(pb[l].y), f2tf(pb[l].z), f2tf(pb[l].w));
        }
        __syncthreads();

        // prefetch next block; latency hides under MMA loop below
        if (kb < 15) {
            const int k0 = (kb + 1) * 32;
            #pragma unroll
            for (int l = 0; l < 4; l++) {
                const int idx = tid + l * 256;
                const int r   = idx >> 3;
                const int c4  = (idx & 7) << 2;
                pa[l] = *(const float4*)&A[(size_t)(row0 + r) * 512 + k0 + c4];
                pb[l] = *(const float4*)&W[(size_t)(col0 + r) * 512 + k0 + c4];
            }
        }

        #pragma unroll
        for (int k8 = 0; k8 < 4; k8++) {
            const int kk = k8 * 8;
            uint32_t af[4][4];
            #pragma unroll
            for (int mt = 0; mt < 4; mt++) {
                const int mr = wm + mt * 16 + g;
                af[mt][0] = As[mr    ][kk + t];
                af[mt][1] = As[mr + 8][kk + t];
                af[mt][2] = As[mr    ][kk + t + 4];
                af[mt][3] = As[mr + 8][kk + t + 4];
            }
            uint32_t bf[4][2];
            #pragma unroll
            for (int nt = 0; nt < 4; nt++) {
                const int nr = wn + nt * 8 + g;
                bf[nt][0] = Bs[nr][kk + t];
                bf[nt][1] = Bs[nr][kk + t + 4];
            }
            #pragma unroll
            for (int mt = 0; mt < 4; mt++)
                #pragma unroll
                for (int nt = 0; nt < 4; nt++)
                    mma_tf32(acc[mt][nt], af[mt], bf[nt]);
        }
        __syncthreads();
    }

    #pragma unroll
    for (int mt = 0; mt < 4; mt++) {
        #pragma unroll
        for (int half = 0; half < 2; half++) {
            const int r = row0 + wm + mt * 16 + g + half * 8;
            const int b = r >> 11;
            const int s = r & 2047;
            #pragma unroll
            for (int nt = 0; nt < 4; nt++) {
                const int j = col0 + wn + nt * 8 + 2 * t;
                float2 v;
                v.x = acc[mt][nt][half * 2 + 0] + __ldg(&bias[j]);
                v.y = acc[mt][nt][half * 2 + 1] + __ldg(&bias[j + 1]);
                if (MODE == 0) {
                    v.x = silu_f(v.x);
                    v.y = silu_f(v.y);
                    const int c   = j >> 9;
                    const int rem = j & 511;
                    if (c == 0) {
                        *(float2*)&g_gate[(size_t)r * 512 + rem] = v;
                    } else {
                        const int head = rem >> 6;
                        const int d    = rem & 63;
                        float* dst = (c == 1) ? g_q : ((c == 2) ? g_k : g_v);
                        *(float2*)&dst[((size_t)(b * 8 + head) * 2048 + s) * 64 + d] = v;
                    }
                } else {
                    *(float2*)&out[(size_t)r * 512 + j] = v;
                }
            }
        }
    }
}

// ---------------------------------------------------------------------------
// Causal HSTU attention on tf32 mma.sync.
// Block: 256 thr = 8 warps (4 M x 2 N), 128-query tile per block (halves
// K/V staging and sync count per MMA vs 64-query tiles). Register prefetch
// of next K/V tile overlaps LDG latency with the MMA loops.
// Per 64-key tile: S = silu(Q K^T /8) masked -> St (tf32 smem),
// then O += St @ V (V staged transposed as Vt[dim][key] = col-major B).
// ---------------------------------------------------------------------------
#define AQST 68   // smem word stride; 68 mod 32 = 4 -> conflict-free frags

__global__ void __launch_bounds__(256) attn_mma_kernel() {
    extern __shared__ uint32_t smw[];
    uint32_t* Qs = smw;                  // [128][AQST] tf32 [query][dim]
    uint32_t* Ks = smw + 128 * AQST;     // [64][AQST]  tf32 [key][dim]
    uint32_t* Vt = smw + 192 * AQST;     // [64][AQST]  tf32 [dim][key]
    uint32_t* St = smw + 256 * AQST;     // [128][AQST] tf32 [query][key]

    const int tid  = threadIdx.x;
    const int wid  = tid >> 5;
    const int lane = tid & 31;
    const int g    = lane >> 2;
    const int t    = lane & 3;
    const int qt   = blockIdx.x;         // 0..15 (128-query tiles)
    const int bh   = blockIdx.y;
    const int b    = bh >> 3;
    const int h    = bh & 7;
    const size_t base = (size_t)bh * SS * HD;
    const float* qp = g_q + base;
    const float* kp = g_k + base;
    const float* vp = g_v + base;
    const int s0 = qt * 128;
    const int wm = (wid >> 1) * 32;      // query offset: 0,32,64,96
    const int wn = (wid & 1) * 32;       // key/dim offset: 0,32

    // Stage Q (128 x 64, tf32)
    #pragma unroll
    for (int l = 0; l < 8; l++) {
        const int idx = tid + l * 256;
        const int r   = idx >> 4;
        const int c4  = (idx & 15) << 2;
        float4 qv = *(const float4*)&qp[(size_t)(s0 + r) * 64 + c4];
        *(uint4*)&Qs[r * AQST + c4] =
            make_uint4(f2tf(qv.x), f2tf(qv.y), f2tf(qv.z), f2tf(qv.w));
    }

    float oacc[2][4][4];
    #pragma unroll
    for (int m = 0; m < 2; m++)
        #pragma unroll
        for (int i = 0; i < 4; i++)
            #pragma unroll
            for (int j = 0; j < 4; j++) oacc[m][i][j] = 0.0f;

    const int last = 2 * qt + 1;

    // prefetch K/V tile 0
    float4 pk[4], pv[4];
    #pragma unroll
    for (int l = 0; l < 4; l++) {
        const int idx = tid + l * 256;
        const int r   = idx >> 4;
        const int c4  = (idx & 15) << 2;
        pk[l] = *(const float4*)&kp[(size_t)r * 64 + c4];
        pv[l] = *(const float4*)&vp[(size_t)r * 64 + c4];
    }

    for (int kt = 0; kt <= last; kt++) {
        const int t0 = kt * 64;
        __syncthreads();   // prev-iter Ks/Vt/St reads done (and Qs staged, kt=0)

        // store prefetched K ([key][dim]) and V transposed ([dim][key])
        #pragma unroll
        for (int l = 0; l < 4; l++) {
            const int idx = tid + l * 256;
            const int r   = idx >> 4;
            const int c4  = (idx & 15) << 2;
            *(uint4*)&Ks[r * AQST + c4] =
                make_uint4(f2tf(pk[l].x), f2tf(pk[l].y), f2tf(pk[l].z), f2tf(pk[l].w));
            Vt[(c4 + 0) * AQST + r] = f2tf(pv[l].x);
            Vt[(c4 + 1) * AQST + r] = f2tf(pv[l].y);
            Vt[(c4 + 2) * AQST + r] = f2tf(pv[l].z);
            Vt[(c4 + 3) * AQST + r] = f2tf(pv[l].w);
        }
        __syncthreads();

        // prefetch next K/V tile; latency hides under the MMA loops
        if (kt < last) {
            const int tn = (kt + 1) * 64;
            #pragma unroll
            for (int l = 0; l < 4; l++) {
                const int idx = tid + l * 256;
                const int r   = idx >> 4;
                const int c4  = (idx & 15) << 2;
                pk[l] = *(const float4*)&kp[(size_t)(tn + r) * 64 + c4];
                pv[l] = *(const float4*)&vp[(size_t)(tn + r) * 64 + c4];
            }
        }

        // ---- GEMM 1: scores = Q @ K^T (per warp: M=32 queries, N=32 keys)
        float sacc[2][4][4];
        #pragma unroll
        for (int m = 0; m < 2; m++)
            #pragma unroll
            for (int i = 0; i < 4; i++)
                #pragma unroll
                for (int j = 0; j < 4; j++) sacc[m][i][j] = 0.0f;

        #pragma unroll
        for (int k8 = 0; k8 < 8; k8++) {
            const int kk = k8 * 8;
            uint32_t af[2][4];
            #pragma unroll
            for (int mt = 0; mt < 2; mt++) {
                const int mr = wm + mt * 16 + g;
                af[mt][0] = Qs[mr * AQST + kk + t];
                af[mt][1] = Qs[(mr + 8) * AQST + kk + t];
                af[mt][2] = Qs[mr * AQST + kk + t + 4];
                af[mt][3] = Qs[(mr + 8) * AQST + kk + t + 4];
            }
            uint32_t bf[4][2];
            #pragma unroll
            for (int nt = 0; nt < 4; nt++) {
                const int nr = wn + nt * 8 + g;
                bf[nt][0] = Ks[nr * AQST + kk + t];
                bf[nt][1] = Ks[nr * AQST + kk + t + 4];
            }
            #pragma unroll
            for (int mt = 0; mt < 2; mt++)
                #pragma unroll
                for (int nt = 0; nt < 4; nt++)
                    mma_tf32(sacc[mt][nt], af[mt], bf[nt]);
        }

        // silu + causal mask on fragments, re-round to tf32 into St
        const bool diag = (kt >= 2 * qt);
        #pragma unroll
        for (int mt = 0; mt < 2; mt++) {
            #pragma unroll
            for (int nt = 0; nt < 4; nt++) {
                const int klocal = wn + nt * 8 + 2 * t;
                const int key    = t0 + klocal;
                #pragma unroll
                for (int half = 0; half < 2; half++) {
                    const int qlocal = wm + mt * 16 + g + half * 8;
                    const int qrow   = s0 + qlocal;
                    float v0 = silu_f(sacc[mt][nt][half * 2 + 0] * 0.125f);
                    float v1 = silu_f(sacc[mt][nt][half * 2 + 1] * 0.125f);
                    if (diag) {
                        if (key     > qrow) v0 = 0.0f;
                        if (key + 1 > qrow) v1 = 0.0f;
                    }
                    *(uint2*)&St[qlocal * AQST + klocal] =
                        make_uint2(f2tf(v0), f2tf(v1));
                }
            }
        }
        __syncthreads();

        // ---- GEMM 2: O += St @ V  (A=St [query][key], B=Vt [dim][key])
        #pragma unroll
        for (int k8 = 0; k8 < 8; k8++) {
            const int kk = k8 * 8;
            uint32_t af[2][4];
            #pragma unroll
            for (int mt = 0; mt < 2; mt++) {
                const int mr = wm + mt * 16 + g;
                af[mt][0] = St[mr * AQST + kk + t];
                af[mt][1] = St[(mr + 8) * AQST + kk + t];
                af[mt][2] = St[mr * AQST + kk + t + 4];
                af[mt][3] = St[(mr + 8) * AQST + kk + t + 4];
            }
            uint32_t bf[4][2];
            #pragma unroll
            for (int nt = 0; nt < 4; nt++) {
                const int nr = wn + nt * 8 + g;
                bf[nt][0] = Vt[nr * AQST + kk + t];
                bf[nt][1] = Vt[nr * AQST + kk + t + 4];
            }
            #pragma unroll
            for (int mt = 0; mt < 2; mt++)
                #pragma unroll
                for (int nt = 0; nt < 4; nt++)
                    mma_tf32(oacc[mt][nt], af[mt], bf[nt]);
        }
    }

    // Write O in [b, s, h*64+dim] layout
    #pragma unroll
    for (int mt = 0; mt < 2; mt++) {
        #pragma unroll
        for (int nt = 0; nt < 4; nt++) {
            const int dim = wn + nt * 8 + 2 * t;
            #pragma unroll
            for (int half = 0; half < 2; half++) {
                const int srow = s0 + wm + mt * 16 + g + half * 8;
                float2 ov = make_float2(oacc[mt][nt][half * 2 + 0],
                                        oacc[mt][nt][half * 2 + 1]);
                *(float2*)&g_o[((size_t)(b * SS + srow)) * DD + h * 64 + dim] = ov;
            }
        }
    }
}

// ---------------------------------------------------------------------------
// LayerNorm(o) * gate  -> g_ng
// ---------------------------------------------------------------------------
__global__ void __launch_bounds__(128) ln_gate_kernel(
    const float* __restrict__ lng, const float* __restrict__ lnb)
{
    const int row = blockIdx.x;
    const int tid = threadIdx.x;
    const float* op = g_o + (size_t)row * DD;

    float4 x = *(const float4*)&op[tid * 4];
    float s = x.x + x.y + x.z + x.w;

    const int lane = tid & 31, wid = tid >> 5;
    __shared__ float r1[4], r2[4];

    #pragma unroll
    for (int off = 16; off; off >>= 1) s += __shfl_xor_sync(0xffffffffu, s, off);
    if (lane == 0) r1[wid] = s;
    __syncthreads();
    const float m = (r1[0] + r1[1] + r1[2] + r1[3]) * (1.0f / 512.0f);

    const float dx = x.x - m, dy = x.y - m, dz = x.z - m, dw = x.w - m;
    float sq = dx * dx + dy * dy + dz * dz + dw * dw;
    #pragma unroll
    for (int off = 16; off; off >>= 1) sq += __shfl_xor_sync(0xffffffffu, sq, off);
    if (lane == 0) r2[wid] = sq;
    __syncthreads();
    const float var = (r2[0] + r2[1] + r2[2] + r2[3]) * (1.0f / 512.0f);
    const float inv = rsqrtf(var + 1e-5f);

    float4 gv = *(const float4*)&lng[tid * 4];
    float4 bv = *(const float4*)&lnb[tid * 4];
    float4 gg = *(const float4*)&g_gate[(size_t)row * DD + tid * 4];
    float4 o;
    o.x = (dx * inv * gv.x + bv.x) * gg.x;
    o.y = (dy * inv * gv.y + bv.y) * gg.y;
    o.z = (dz * inv * gv.z + bv.z) * gg.z;
    o.w = (dw * inv * gv.w + bv.w) * gg.w;
    *(float4*)&g_ng[(size_t)row * DD + tid * 4] = o;
}

// ---------------------------------------------------------------------------
extern "C" void kernel_launch(void* const* d_in, const int* in_sizes, int n_in,
                              void* d_out, int out_size) {
    const float* x   = (const float*)d_in[0];
    const float* W1  = (const float*)d_in[1];
    const float* b1  = (const float*)d_in[2];
    const float* lng = (const float*)d_in[3];
    const float* lnb = (const float*)d_in[4];
    const float* W2  = (const float*)d_in[5];
    const float* b2  = (const float*)d_in[6];
    float* out = (float*)d_out;

    const int attn_smem = 384 * AQST * (int)sizeof(uint32_t);  // 104448 B
    cudaFuncSetAttribute(attn_mma_kernel,
                         cudaFuncAttributeMaxDynamicSharedMemorySize, attn_smem);

    // 1) h = silu(x @ W1^T + b1), scattered to gate/q/k/v   (tf32 mma.sync)
    tc_gemm<0><<<dim3(2048 / 128, MROWS / 128), 256>>>(x, W1, b1, out);

    // 2) causal silu-attention -> g_o [b,s,d]               (tf32 mma.sync)
    attn_mma_kernel<<<dim3(SS / 128, BB * HH), 256, attn_smem>>>();

    // 3) layernorm(o) * gate -> g_ng
    ln_gate_kernel<<<MROWS, 128>>>(lng, lnb);

    // 4) out = g_ng @ W2^T + b2                             (tf32 mma.sync)
    tc_gemm<1><<<dim3(512 / 128, MROWS / 128), 256>>>(nullptr, W2, b2, out);
}